// round 12
// baseline (speedup 1.0000x reference)
#include <cuda_runtime.h>
#include <math.h>

// ---------------------------------------------------------------------------
// DCTModel collapsed to a single kernel:
//   out[b, cq*54+m(u,v), i, j] =
//     sum_{r,s<3} W[i][u][r] * W[j][v][s] * t[b,cq, base_i+r, base_j+s]
//   t = 127.5 * (RGB2YCBCR @ x);  additive constants only hit the dropped DC.
//
// R11: L1tex binder = per-lane j-weight LDS (64 of ~135 wf/warp). Each thread
// now handles 2 adjacent i-rows with the SAME j-pair, so every wa/wb LDS.128
// feeds 4 dots instead of 2 -> weight-LDS per output halves. Block = 112
// threads (56 pairs x 2 thread-rows, covering 4 i-rows); grid stays 1344
// (R9 lesson: preserve block parallelism + narrow write footprint).
// ---------------------------------------------------------------------------

#define HW 112
#define NPLANE 12544
#define NBATCH 16

#define BX 56            // j-pairs per block
#define BYT 2            // thread-rows (each thread does 2 adjacent i)
#define NTHREADS (BX*BYT)   // 112
#define ROWS_T 6
#define COLS_T 114
#define PLANE_T (ROWS_T*COLS_T)   // 684
#define NIT ((PLANE_T + NTHREADS - 1) / NTHREADS)  // 7
#define PSTRIDE 68       // floats per pair in sW4 (64 data + 4 pad)

__constant__ float c_M[3][3] = {
    { 0.299f,     0.587f,    0.114f    },
    {-0.168736f, -0.331264f, 0.5f      },
    { 0.5f,      -0.418688f, -0.081312f}
};

// SUB_CHANNELS = {0,1,2,3,4,5,8,9,16,24}
#define SUB_MASK 0x000000000101033FULL

// ---------------------------------------------------------------------------
// cos(k*pi/16), constexpr -> folded to FFMA immediates in unrolled loops.
// ---------------------------------------------------------------------------
__host__ __device__ constexpr float cosw(int k) {
    const double T[9] = {
        1.0,
        0.98078528040323044913,
        0.92387953251128675613,
        0.83146961230254523708,
        0.70710678118654752440,
        0.55557023301960222474,
        0.38268343236508977173,
        0.19509032201612826785,
        0.0
    };
    k &= 31;
    if (k > 16) k = 32 - k;
    double s = 1.0;
    if (k > 8) { s = -1.0; k = 16 - k; }
    return (float)(s * T[k]);
}

// base index: src is monotone in x, so base = i0[x=0]
__device__ __forceinline__ int comp_base(int idx) {
    float src = (float)(8 * idx * 111) / 895.0f;
    int f = (int)floorf(src);
    return (f > HW - 2) ? (HW - 2) : f;
}

// Fused (DCT x upsample) weights for one block index: W[v][k], k<3.
__device__ __forceinline__ void comp_weights(int idx, float W[8][3]) {
    const int base = comp_base(idx);
    float A0[8], A1[8], A2[8];
    #pragma unroll
    for (int x = 0; x < 8; x++) {
        float src = (float)((8 * idx + x) * 111) / 895.0f;
        int f = (int)floorf(src);
        if (f > HW - 2) f = HW - 2;
        float w = src - (float)f;
        bool z = (f == base);           // offset 0 or 1
        A0[x] = z ? 1.0f - w : 0.0f;
        A1[x] = z ? w        : 1.0f - w;
        A2[x] = z ? 0.0f     : w;
    }
    #pragma unroll
    for (int v = 0; v < 8; v++) {
        float s0 = 0.f, s1 = 0.f, s2 = 0.f;
        #pragma unroll
        for (int x = 0; x < 8; x++) {
            const float c = cosw((2 * x + 1) * v);   // compile-time immediate
            s0 = fmaf(c, A0[x], s0);
            s1 = fmaf(c, A1[x], s1);
            s2 = fmaf(c, A2[x], s2);
        }
        const float sc = (v == 0) ? 0.35355339059327373f : 0.5f;  // alpha_v/2
        W[v][0] = s0 * sc; W[v][1] = s1 * sc; W[v][2] = s2 * sc;
    }
}

// ---------------------------------------------------------------------------
// Single kernel: block = (56 j-pairs, 2 thread-rows); grid = (28, 3 cq, 16 b).
// Each thread computes 2 adjacent i-rows sharing its j-pair weights.
// ---------------------------------------------------------------------------
__global__ __launch_bounds__(NTHREADS, 6)
void dct_main_kernel(const float* __restrict__ x, float* __restrict__ out) {
    __shared__ __align__(16) float sW4[BX * PSTRIDE]; // 15.2 KB
    __shared__ float sR[4 * 25];                      // row weights (4 rows)
    __shared__ float sT[PLANE_T];                     // YCbCr tile (one cq)

    const int tx  = threadIdx.x;            // 0..55
    const int ty  = threadIdx.y;            // 0..1
    const int tid = ty * BX + tx;
    const int cq  = blockIdx.y;
    const int b   = blockIdx.z;
    const int i0  = blockIdx.x * 4;         // block covers 4 i-rows

    const int rmin = comp_base(i0);

    // ---- phase 1: issue ALL tile LDGs first (latency overlapped below) ----
    float p0[NIT], p1[NIT], p2[NIT];
    {
        const float* xb = x + (size_t)b * 3 * NPLANE;
        #pragma unroll
        for (int it = 0; it < NIT; it++) {
            int e = tid + it * NTHREADS;
            bool ok = (e < PLANE_T);
            int ec = ok ? e : 0;
            int lr = ec / COLS_T, c = ec - lr * COLS_T;
            int srow = rmin + lr; if (srow > HW - 1) srow = HW - 1;
            int scol = c;         if (scol > HW - 1) scol = HW - 1;
            int off = srow * HW + scol;
            p0[it] = ok ? __ldg(xb + off)              : 0.f;
            p1[it] = ok ? __ldg(xb + NPLANE + off)     : 0.f;
            p2[it] = ok ? __ldg(xb + 2 * NPLANE + off) : 0.f;
        }
    }

    // ---- phase 2: weight construction (ALU overlaps the loads above) ------
    {
        const int j = tid;                  // all 112 threads: one j column
        float W[8][3];
        comp_weights(j, W);
        const bool sh = (comp_base(j) - comp_base(j & ~1)) != 0;  // pair shift
        float* dst = &sW4[(j >> 1) * PSTRIDE + (j & 1) * 4];
        #pragma unroll
        for (int v = 0; v < 8; v++) {
            dst[v * 8 + 0] = sh ? 0.0f    : W[v][0];
            dst[v * 8 + 1] = sh ? W[v][0] : W[v][1];
            dst[v * 8 + 2] = sh ? W[v][1] : W[v][2];
            dst[v * 8 + 3] = sh ? W[v][2] : 0.0f;
        }
    }
    if (tid < 4) {                          // 4 threads also do row weights
        float W[8][3];
        comp_weights(i0 + tid, W);
        #pragma unroll
        for (int u = 0; u < 8; u++) {
            sR[tid * 25 + u * 3 + 0] = W[u][0];
            sR[tid * 25 + u * 3 + 1] = W[u][1];
            sR[tid * 25 + u * 3 + 2] = W[u][2];
        }
    }

    // ---- phase 3: combine loaded pixels -> YCbCr, store tile --------------
    {
        const float m0 = 127.5f * c_M[cq][0];
        const float m1 = 127.5f * c_M[cq][1];
        const float m2 = 127.5f * c_M[cq][2];
        #pragma unroll
        for (int it = 0; it < NIT; it++) {
            int e = tid + it * NTHREADS;
            if (e < PLANE_T)
                sT[e] = fmaf(m0, p0[it], fmaf(m1, p1[it], m2 * p2[it]));
        }
    }
    __syncthreads();

    // ---- per-thread work: rows iA, iB = iA+1 share the j-pair -------------
    const int iA  = i0 + 2 * ty;
    const int iB  = iA + 1;
    const int j0  = 2 * tx;
    const int bj0 = comp_base(j0);
    const int lrA = comp_base(iA) - rmin;   // 0..3
    const int lrB = comp_base(iB) - rmin;

    // gvA / gvB: row-contracted 4-wide vectors per u
    float gvA[8][4], gvB[8][4];
    {
        float t[3][4];
        #pragma unroll
        for (int r = 0; r < 3; r++) {
            const float* row = &sT[(lrA + r) * COLS_T + bj0];
            #pragma unroll
            for (int s = 0; s < 4; s++) t[r][s] = row[s];
        }
        const float* wr = &sR[(2 * ty) * 25];
        #pragma unroll
        for (int u = 0; u < 8; u++) {
            float w0 = wr[u * 3 + 0], w1 = wr[u * 3 + 1], w2 = wr[u * 3 + 2];
            #pragma unroll
            for (int s = 0; s < 4; s++)
                gvA[u][s] = fmaf(w0, t[0][s], fmaf(w1, t[1][s], w2 * t[2][s]));
        }
    }
    {
        float t[3][4];
        #pragma unroll
        for (int r = 0; r < 3; r++) {
            const float* row = &sT[(lrB + r) * COLS_T + bj0];
            #pragma unroll
            for (int s = 0; s < 4; s++) t[r][s] = row[s];
        }
        const float* wr = &sR[(2 * ty + 1) * 25];
        #pragma unroll
        for (int u = 0; u < 8; u++) {
            float w0 = wr[u * 3 + 0], w1 = wr[u * 3 + 1], w2 = wr[u * 3 + 2];
            #pragma unroll
            for (int s = 0; s < 4; s++)
                gvB[u][s] = fmaf(w0, t[0][s], fmaf(w1, t[1][s], w2 * t[2][s]));
        }
    }

    // Epilogue: each wa/wb LDS.128 feeds 4 dots (2 rows x 2 j)
    float* outpA = out + ((size_t)(b * 162 + cq * 54)) * NPLANE + iA * HW + j0;
    float* outpB = outpA + HW;
    const float* wp = &sW4[tx * PSTRIDE];

    #pragma unroll
    for (int v = 0; v < 8; v++) {
        const float4 wa = *reinterpret_cast<const float4*>(wp + v * 8);
        const float4 wb = *reinterpret_cast<const float4*>(wp + v * 8 + 4);
        #pragma unroll
        for (int u = 0; u < 8; u++) {
            const int idx = u * 8 + v;
            if ((SUB_MASK >> idx) & 1ULL) continue;
            const int m = idx - __popcll(SUB_MASK & ((1ULL << idx) - 1ULL));
            float2 vA, vB;
            vA.x = fmaf(gvA[u][0], wa.x, fmaf(gvA[u][1], wa.y,
                   fmaf(gvA[u][2], wa.z, gvA[u][3] * wa.w)));
            vA.y = fmaf(gvA[u][0], wb.x, fmaf(gvA[u][1], wb.y,
                   fmaf(gvA[u][2], wb.z, gvA[u][3] * wb.w)));
            vB.x = fmaf(gvB[u][0], wa.x, fmaf(gvB[u][1], wa.y,
                   fmaf(gvB[u][2], wa.z, gvB[u][3] * wa.w)));
            vB.y = fmaf(gvB[u][0], wb.x, fmaf(gvB[u][1], wb.y,
                   fmaf(gvB[u][2], wb.z, gvB[u][3] * wb.w)));
            *reinterpret_cast<float2*>(outpA + (size_t)m * NPLANE) = vA;
            *reinterpret_cast<float2*>(outpB + (size_t)m * NPLANE) = vB;
        }
    }
}

// ---------------------------------------------------------------------------
extern "C" void kernel_launch(void* const* d_in, const int* in_sizes, int n_in,
                              void* d_out, int out_size) {
    const float* x = (const float*)d_in[0];   // (16, 3, 112, 112) fp32
    float* out = (float*)d_out;               // (16, 162, 112, 112) fp32

    dim3 block(BX, BYT);                      // 112 threads
    dim3 grid(HW / 4, 3, NBATCH);             // (28, 3, 16) = 1344 blocks
    dct_main_kernel<<<grid, block>>>(x, out);
}

// round 13
// speedup vs baseline: 1.1151x; 1.1151x over previous
#include <cuda_runtime.h>
#include <math.h>

// ---------------------------------------------------------------------------
// DCTModel collapsed to a single kernel:
//   out[b, cq*54+m(u,v), i, j] =
//     sum_{r,s<3} W[i][u][r] * W[j][v][s] * t[b,cq, base_i+r, base_j+s]
//   t = 127.5 * (RGB2YCBCR @ x);  additive constants only hit the dropped DC.
//
// R12: revert to R10 shape (1 row/thread, 224-thread blocks, grid 1344; R11's
// 2-rows/thread lost via regs 80 + 3.5-warp blocks -> occ 30%). The kernel is
// latency-limited at ~50% issue; regs (72) cap occupancy at 4 blocks/SM
// (64.5K of 64K regs). Changes:
//   - prologue load->combine->STS merged per element (kills the 12-reg
//     prefetch arrays that peaked prologue pressure)
//   - __launch_bounds__(224, 5): force <=58 regs -> 5 blocks/SM, 35 warps
// ---------------------------------------------------------------------------

#define HW 112
#define NPLANE 12544
#define NBATCH 16

#define BX 56           // j-pairs per block
#define BY 4            // i rows per block
#define NTHREADS (BX*BY)
#define ROWS_T 6
#define COLS_T 114
#define PLANE_T (ROWS_T*COLS_T)   // 684
#define PSTRIDE 68      // floats per pair in sW4 (64 data + 4 pad)

__constant__ float c_M[3][3] = {
    { 0.299f,     0.587f,    0.114f    },
    {-0.168736f, -0.331264f, 0.5f      },
    { 0.5f,      -0.418688f, -0.081312f}
};

// SUB_CHANNELS = {0,1,2,3,4,5,8,9,16,24}
#define SUB_MASK 0x000000000101033FULL

// ---------------------------------------------------------------------------
// cos(k*pi/16), constexpr -> folded to FFMA immediates in unrolled loops.
// ---------------------------------------------------------------------------
__host__ __device__ constexpr float cosw(int k) {
    const double T[9] = {
        1.0,
        0.98078528040323044913,
        0.92387953251128675613,
        0.83146961230254523708,
        0.70710678118654752440,
        0.55557023301960222474,
        0.38268343236508977173,
        0.19509032201612826785,
        0.0
    };
    k &= 31;
    if (k > 16) k = 32 - k;
    double s = 1.0;
    if (k > 8) { s = -1.0; k = 16 - k; }
    return (float)(s * T[k]);
}

// base index: src is monotone in x, so base = i0[x=0]
__device__ __forceinline__ int comp_base(int idx) {
    float src = (float)(8 * idx * 111) / 895.0f;
    int f = (int)floorf(src);
    return (f > HW - 2) ? (HW - 2) : f;
}

// Fused (DCT x upsample) weights for one block index: W[v][k], k<3.
__device__ __forceinline__ void comp_weights(int idx, float W[8][3]) {
    const int base = comp_base(idx);
    float A0[8], A1[8], A2[8];
    #pragma unroll
    for (int x = 0; x < 8; x++) {
        float src = (float)((8 * idx + x) * 111) / 895.0f;
        int f = (int)floorf(src);
        if (f > HW - 2) f = HW - 2;
        float w = src - (float)f;
        bool z = (f == base);           // offset 0 or 1
        A0[x] = z ? 1.0f - w : 0.0f;
        A1[x] = z ? w        : 1.0f - w;
        A2[x] = z ? 0.0f     : w;
    }
    #pragma unroll
    for (int v = 0; v < 8; v++) {
        float s0 = 0.f, s1 = 0.f, s2 = 0.f;
        #pragma unroll
        for (int x = 0; x < 8; x++) {
            const float c = cosw((2 * x + 1) * v);   // compile-time immediate
            s0 = fmaf(c, A0[x], s0);
            s1 = fmaf(c, A1[x], s1);
            s2 = fmaf(c, A2[x], s2);
        }
        const float sc = (v == 0) ? 0.35355339059327373f : 0.5f;  // alpha_v/2
        W[v][0] = s0 * sc; W[v][1] = s1 * sc; W[v][2] = s2 * sc;
    }
}

// ---------------------------------------------------------------------------
// Single kernel: block = (56 j-pairs, 4 i-rows); grid = (28, 3 cq, 16 b).
// ---------------------------------------------------------------------------
__global__ __launch_bounds__(NTHREADS, 5)
void dct_main_kernel(const float* __restrict__ x, float* __restrict__ out) {
    __shared__ __align__(16) float sW4[BX * PSTRIDE]; // 15.2 KB
    __shared__ float sR[BY * 25];                     // row weights (padded)
    __shared__ float sT[PLANE_T];                     // YCbCr tile (one cq)

    const int tx  = threadIdx.x;            // 0..55
    const int ty  = threadIdx.y;            // 0..3
    const int tid = ty * BX + tx;
    const int cq  = blockIdx.y;
    const int b   = blockIdx.z;
    const int i0  = blockIdx.x * BY;

    const int rmin = comp_base(i0);

    // ---- YCbCr tile: load -> combine -> STS, minimal live registers -------
    {
        const float m0 = 127.5f * c_M[cq][0];
        const float m1 = 127.5f * c_M[cq][1];
        const float m2 = 127.5f * c_M[cq][2];
        const float* xb = x + (size_t)b * 3 * NPLANE;
        for (int e = tid; e < PLANE_T; e += NTHREADS) {
            int lr = e / COLS_T, c = e - lr * COLS_T;
            int srow = rmin + lr; if (srow > HW - 1) srow = HW - 1;
            int scol = c;         if (scol > HW - 1) scol = HW - 1;
            int off = srow * HW + scol;
            float p0 = __ldg(xb + off);
            float p1 = __ldg(xb + NPLANE + off);
            float p2 = __ldg(xb + 2 * NPLANE + off);
            sT[e] = fmaf(m0, p0, fmaf(m1, p1, m2 * p2));
        }
    }

    // ---- weight construction (overlaps other warps' loads) ----------------
    if (tid < HW) {
        const int j = tid;
        float W[8][3];
        comp_weights(j, W);
        const bool sh = (comp_base(j) - comp_base(j & ~1)) != 0;  // pair shift
        float* dst = &sW4[(j >> 1) * PSTRIDE + (j & 1) * 4];
        #pragma unroll
        for (int v = 0; v < 8; v++) {
            dst[v * 8 + 0] = sh ? 0.0f    : W[v][0];
            dst[v * 8 + 1] = sh ? W[v][0] : W[v][1];
            dst[v * 8 + 2] = sh ? W[v][1] : W[v][2];
            dst[v * 8 + 3] = sh ? W[v][2] : 0.0f;
        }
    } else if (tid < HW + BY) {
        const int r = tid - HW;
        float W[8][3];
        comp_weights(i0 + r, W);
        #pragma unroll
        for (int u = 0; u < 8; u++) {
            sR[r * 25 + u * 3 + 0] = W[u][0];
            sR[r * 25 + u * 3 + 1] = W[u][1];
            sR[r * 25 + u * 3 + 2] = W[u][2];
        }
    }
    __syncthreads();

    // ---- per-thread work --------------------------------------------------
    const int i   = i0 + ty;
    const int j0  = 2 * tx;
    const int bj0 = comp_base(j0);
    const int lr  = comp_base(i) - rmin;     // 0..3

    float t[3][4];
    #pragma unroll
    for (int r = 0; r < 3; r++) {
        const float* row = &sT[(lr + r) * COLS_T + bj0];
        #pragma unroll
        for (int s = 0; s < 4; s++) t[r][s] = row[s];
    }

    // gv[u][s] = sum_r W[i][u][r] * t[r][s]
    float gv[8][4];
    {
        const float* wr = &sR[ty * 25];
        #pragma unroll
        for (int u = 0; u < 8; u++) {
            float w0 = wr[u * 3 + 0], w1 = wr[u * 3 + 1], w2 = wr[u * 3 + 2];
            #pragma unroll
            for (int s = 0; s < 4; s++)
                gv[u][s] = fmaf(w0, t[0][s], fmaf(w1, t[1][s], w2 * t[2][s]));
        }
    }

    // Epilogue: 27 float2 stores; two 4-wide dots per kept (u,v)
    float* outp = out + ((size_t)(b * 162 + cq * 54)) * NPLANE + i * HW + j0;
    const float* wp = &sW4[tx * PSTRIDE];

    #pragma unroll
    for (int v = 0; v < 8; v++) {
        const float4 wa = *reinterpret_cast<const float4*>(wp + v * 8);
        const float4 wb = *reinterpret_cast<const float4*>(wp + v * 8 + 4);
        #pragma unroll
        for (int u = 0; u < 8; u++) {
            const int idx = u * 8 + v;
            if ((SUB_MASK >> idx) & 1ULL) continue;
            const int m = idx - __popcll(SUB_MASK & ((1ULL << idx) - 1ULL));
            float2 val;
            val.x = fmaf(gv[u][0], wa.x, fmaf(gv[u][1], wa.y,
                    fmaf(gv[u][2], wa.z, gv[u][3] * wa.w)));
            val.y = fmaf(gv[u][0], wb.x, fmaf(gv[u][1], wb.y,
                    fmaf(gv[u][2], wb.z, gv[u][3] * wb.w)));
            *reinterpret_cast<float2*>(outp + (size_t)m * NPLANE) = val;
        }
    }
}

// ---------------------------------------------------------------------------
extern "C" void kernel_launch(void* const* d_in, const int* in_sizes, int n_in,
                              void* d_out, int out_size) {
    const float* x = (const float*)d_in[0];   // (16, 3, 112, 112) fp32
    float* out = (float*)d_out;               // (16, 162, 112, 112) fp32

    dim3 block(BX, BY);                       // 224 threads
    dim3 grid(HW / BY, 3, NBATCH);            // (28, 3, 16) = 1344 blocks
    dct_main_kernel<<<grid, block>>>(x, out);
}